// round 1
// baseline (speedup 1.0000x reference)
#include <cuda_runtime.h>
#include <cuda_bf16.h>
#include <math.h>

// ---------------- problem constants ----------------
#define T_SEQ   2048
#define HID     2048
#define NUM_K   16
#define NUM_V   32
#define DK      128
#define DV      128
#define KEY_DIM 2048            // NUM_K*DK
#define VAL_DIM 4096            // NUM_V*DV
#define CONV_DIM 8192           // 2*KEY_DIM + VAL_DIM
#define QKVZ_N  12288           // 2*KEY_DIM + 2*VAL_DIM
#define QSCALE  0.08838834764831845f   // 128^-0.5

// ---------------- scratch (device globals; no cudaMalloc allowed) ----------------
__device__ float  g_qkvz  [T_SEQ * QKVZ_N];        // post GEMM1: [q k v z]
__device__ float  g_qkv   [T_SEQ * CONV_DIM];      // post conv+silu: [q k v]
__device__ float  g_ba    [T_SEQ * 64];            // [b(32) a(32)]
__device__ float2 g_egbeta[T_SEQ * NUM_V];         // (exp(g), beta)
__device__ float  g_qhat  [T_SEQ * KEY_DIM];       // l2norm(q)*scale, [T,16,128]
__device__ float  g_khat  [T_SEQ * KEY_DIM];       // l2norm(k),       [T,16,128]
__device__ float  g_oscan [T_SEQ * VAL_DIM];       // scan output [T,32,128]
__device__ float  g_gated [T_SEQ * VAL_DIM];       // post rmsnorm*silu(z)

// ---------------- helpers ----------------
__device__ __forceinline__ float sigmoidf_(float x) { return 1.0f / (1.0f + __expf(-x)); }
__device__ __forceinline__ float siluf_(float x)    { return x * sigmoidf_(x); }

// ---------------- SGEMM: C[M,N] = A[M,K] @ B[K,N], row-major, fp32 ----------------
// 128x128 block tile, BK=8, 256 threads, 8x8 per thread, register-prefetched loads.
// Requires M%128==0, N%128==0, K%8==0.
__global__ __launch_bounds__(256) void sgemm128(
    const float* __restrict__ A, const float* __restrict__ B, float* __restrict__ C,
    int M, int N, int K)
{
    __shared__ float As[8][128];
    __shared__ float Bs[8][128];

    const int tid = threadIdx.x;
    const int bm  = blockIdx.y * 128;
    const int bn  = blockIdx.x * 128;

    const int aRow = tid >> 1;           // 0..127
    const int aCol = (tid & 1) << 2;     // 0 or 4
    const int bRow = tid >> 5;           // 0..7
    const int bCol = (tid & 31) << 2;    // 0..124

    const int tx = (tid & 15) << 3;      // 0..120 (C col offset)
    const int ty = (tid >> 4) << 3;      // 0..120 (C row offset)

    const float* Aptr = A + (size_t)(bm + aRow) * K + aCol;
    const float* Bptr = B + (size_t)bRow * N + bn + bCol;

    float acc[8][8];
#pragma unroll
    for (int i = 0; i < 8; ++i)
#pragma unroll
        for (int j = 0; j < 8; ++j) acc[i][j] = 0.0f;

    float4 a_reg = *(const float4*)Aptr;
    float4 b_reg = *(const float4*)Bptr;

    const int nk = K >> 3;
    for (int kt = 0; kt < nk; ++kt) {
        // stage current tile into smem (A transposed)
        As[aCol + 0][aRow] = a_reg.x;
        As[aCol + 1][aRow] = a_reg.y;
        As[aCol + 2][aRow] = a_reg.z;
        As[aCol + 3][aRow] = a_reg.w;
        *(float4*)&Bs[bRow][bCol] = b_reg;
        __syncthreads();

        // prefetch next tile
        if (kt + 1 < nk) {
            a_reg = *(const float4*)(Aptr + (size_t)(kt + 1) * 8);
            b_reg = *(const float4*)(Bptr + (size_t)(kt + 1) * 8 * N);
        }

#pragma unroll
        for (int kk = 0; kk < 8; ++kk) {
            float ra[8], rb[8];
            *(float4*)(ra + 0) = *(const float4*)&As[kk][ty];
            *(float4*)(ra + 4) = *(const float4*)&As[kk][ty + 4];
            *(float4*)(rb + 0) = *(const float4*)&Bs[kk][tx];
            *(float4*)(rb + 4) = *(const float4*)&Bs[kk][tx + 4];
#pragma unroll
            for (int i = 0; i < 8; ++i)
#pragma unroll
                for (int j = 0; j < 8; ++j)
                    acc[i][j] = fmaf(ra[i], rb[j], acc[i][j]);
        }
        __syncthreads();
    }

#pragma unroll
    for (int i = 0; i < 8; ++i) {
        float* Crow = C + (size_t)(bm + ty + i) * N + bn + tx;
        *(float4*)(Crow + 0) = make_float4(acc[i][0], acc[i][1], acc[i][2], acc[i][3]);
        *(float4*)(Crow + 4) = make_float4(acc[i][4], acc[i][5], acc[i][6], acc[i][7]);
    }
}

// ---------------- small GEMM: ba = h @ W_ba  (2048x64, K=2048) ----------------
__global__ __launch_bounds__(64) void gemm_ba(
    const float* __restrict__ A, const float* __restrict__ B, float* __restrict__ C)
{
    __shared__ float hrow[HID];
    const int row = blockIdx.x;
    const int tid = threadIdx.x;   // 0..63 = output column
    for (int i = tid; i < HID; i += 64) hrow[i] = A[(size_t)row * HID + i];
    __syncthreads();
    float acc = 0.0f;
#pragma unroll 8
    for (int k = 0; k < HID; ++k)
        acc = fmaf(hrow[k], B[(size_t)k * 64 + tid], acc);
    C[(size_t)row * 64 + tid] = acc;
}

// ---------------- causal depthwise conv (K=4) + SiLU ----------------
// x = first CONV_DIM columns of qkvz; y[t][c] = silu(sum_j w[c][j]*x[t-3+j][c])
__global__ __launch_bounds__(256) void conv_silu(
    const float* __restrict__ qkvz, const float* __restrict__ conv_w,
    float* __restrict__ out)
{
    int idx = blockIdx.x * blockDim.x + threadIdx.x;   // t*CONV_DIM + c
    if (idx >= T_SEQ * CONV_DIM) return;
    int t = idx >> 13;           // / 8192
    int c = idx & (CONV_DIM - 1);
    const float* w = conv_w + c * 4;
    float acc = w[3] * qkvz[(size_t)t * QKVZ_N + c];
    if (t >= 1) acc = fmaf(w[2], qkvz[(size_t)(t - 1) * QKVZ_N + c], acc);
    if (t >= 2) acc = fmaf(w[1], qkvz[(size_t)(t - 2) * QKVZ_N + c], acc);
    if (t >= 3) acc = fmaf(w[0], qkvz[(size_t)(t - 3) * QKVZ_N + c], acc);
    out[idx] = siluf_(acc);
}

// ---------------- gating: eg = exp(-exp(A_log)*softplus(a+dt_bias)); beta = sigmoid(b) ----------------
__global__ __launch_bounds__(256) void gate_prep(
    const float* __restrict__ ba, const float* __restrict__ A_log,
    const float* __restrict__ dt_bias, float2* __restrict__ egbeta)
{
    int i = blockIdx.x * blockDim.x + threadIdx.x;   // t*32 + h
    if (i >= T_SEQ * NUM_V) return;
    int t = i >> 5;
    int h = i & 31;
    float b = ba[(size_t)t * 64 + h];
    float a = ba[(size_t)t * 64 + 32 + h];
    float x = a + dt_bias[h];
    float sp = (x > 20.0f) ? x : log1pf(expf(x));
    float g = -expf(A_log[h]) * sp;
    egbeta[i] = make_float2(expf(g), sigmoidf_(b));
}

// ---------------- l2norm of q and k per (t, key-head); scale folded into q ----------------
// one warp per 128-float row
__global__ __launch_bounds__(256) void l2norm_qk(
    const float* __restrict__ qkv, float* __restrict__ qhat, float* __restrict__ khat)
{
    int gid  = blockIdx.x * 8 + (threadIdx.x >> 5);   // warp id over 2048*32
    int lane = threadIdx.x & 31;
    int t   = gid >> 5;
    int sub = gid & 31;
    int kh  = sub & 15;
    int isK = sub >> 4;
    const float* src = qkv + (size_t)t * CONV_DIM + isK * KEY_DIM + kh * DK;
    float4 x = *(const float4*)(src + lane * 4);
    float s = x.x * x.x + x.y * x.y + x.z * x.z + x.w * x.w;
#pragma unroll
    for (int off = 16; off > 0; off >>= 1) s += __shfl_xor_sync(0xffffffffu, s, off);
    float r = rsqrtf(s + 1e-6f);
    if (!isK) r *= QSCALE;
    float* dst = (isK ? khat : qhat) + (size_t)t * KEY_DIM + kh * DK;
    *(float4*)(dst + lane * 4) = make_float4(x.x * r, x.y * r, x.z * r, x.w * r);
}

// ---------------- gated delta scan: one warp per (head, v-column) ----------------
// S[:,v] recurrence; o_v = eg*(qhat.S) + (qhat.khat)*delta_v
__global__ __launch_bounds__(256) void gdn_scan(
    const float* __restrict__ qhat, const float* __restrict__ khat,
    const float* __restrict__ qkv, const float2* __restrict__ egbeta,
    float* __restrict__ o)
{
    const int warp = threadIdx.x >> 5;
    const int lane = threadIdx.x & 31;
    const int h   = blockIdx.x >> 4;                    // 0..31
    const int col = ((blockIdx.x & 15) << 3) + warp;    // 0..127
    const int kh  = h >> 1;                             // GQA repeat=2

    const float4* kp = (const float4*)(khat + kh * DK) + lane;     // +512 per t
    const float4* qp = (const float4*)(qhat + kh * DK) + lane;
    const float*  vp = qkv + 2 * KEY_DIM + h * DV + col;           // +8192 per t
    const float2* ep = egbeta + h;                                 // +32 per t
    float*        op = o + h * DV + col;                           // +4096 per t

    float S0 = 0.f, S1 = 0.f, S2 = 0.f, S3 = 0.f;

    float4 kk = *kp, qq = *qp;
    float  vt = *vp;
    float2 eb = *ep;

    for (int t = 0; t < T_SEQ; ++t) {
        float4 kk_n, qq_n; float vt_n; float2 eb_n;
        if (t < T_SEQ - 1) {
            kp += KEY_DIM / 4; qp += KEY_DIM / 4; vp += CONV_DIM; ep += NUM_V;
            kk_n = *kp; qq_n = *qp; vt_n = *vp; eb_n = *ep;
        } else {
            kk_n = kk; qq_n = qq; vt_n = vt; eb_n = eb;
        }

        float dk  = kk.x * S0 + kk.y * S1 + kk.z * S2 + kk.w * S3;
        float dq  = qq.x * S0 + qq.y * S1 + qq.z * S2 + qq.w * S3;
        float dqk = qq.x * kk.x + qq.y * kk.y + qq.z * kk.z + qq.w * kk.w;
#pragma unroll
        for (int off = 16; off > 0; off >>= 1) {
            dk  += __shfl_xor_sync(0xffffffffu, dk,  off);
            dq  += __shfl_xor_sync(0xffffffffu, dq,  off);
            dqk += __shfl_xor_sync(0xffffffffu, dqk, off);
        }
        const float eg = eb.x, beta = eb.y;
        const float kv    = eg * dk;
        const float delta = (vt - kv) * beta;
        const float ot    = fmaf(eg, dq, dqk * delta);
        S0 = fmaf(S0, eg, kk.x * delta);
        S1 = fmaf(S1, eg, kk.y * delta);
        S2 = fmaf(S2, eg, kk.z * delta);
        S3 = fmaf(S3, eg, kk.w * delta);
        if (lane == 0) *op = ot;
        op += VAL_DIM;
        kk = kk_n; qq = qq_n; vt = vt_n; eb = eb_n;
    }
}

// ---------------- RMSNorm (mean over DV) * norm_w * silu(z) ----------------
__global__ __launch_bounds__(256) void rms_gate(
    const float* __restrict__ o, const float* __restrict__ qkvz,
    const float* __restrict__ norm_w, float* __restrict__ gated)
{
    int gid  = blockIdx.x * 8 + (threadIdx.x >> 5);   // warp per (t,h)
    int lane = threadIdx.x & 31;
    int t = gid >> 5;
    int h = gid & 31;
    const float* orow = o + (size_t)t * VAL_DIM + h * DV;
    float4 x = *(const float4*)(orow + lane * 4);
    float s = x.x * x.x + x.y * x.y + x.z * x.z + x.w * x.w;
#pragma unroll
    for (int off = 16; off > 0; off >>= 1) s += __shfl_xor_sync(0xffffffffu, s, off);
    float r = rsqrtf(s * (1.0f / DV) + 1e-6f);
    float4 z  = *(const float4*)(qkvz + (size_t)t * QKVZ_N + 2 * KEY_DIM + VAL_DIM + h * DV + lane * 4);
    float4 nw = *(const float4*)(norm_w + lane * 4);
    float4 y;
    y.x = x.x * r * nw.x * siluf_(z.x);
    y.y = x.y * r * nw.y * siluf_(z.y);
    y.z = x.z * r * nw.z * siluf_(z.z);
    y.w = x.w * r * nw.w * siluf_(z.w);
    *(float4*)(gated + (size_t)t * VAL_DIM + h * DV + lane * 4) = y;
}

// ---------------- launch ----------------
extern "C" void kernel_launch(void* const* d_in, const int* in_sizes, int n_in,
                              void* d_out, int out_size)
{
    const float* h_in    = (const float*)d_in[0];
    const float* W_qkvz  = (const float*)d_in[1];
    const float* W_ba    = (const float*)d_in[2];
    const float* conv_w  = (const float*)d_in[3];
    const float* dt_bias = (const float*)d_in[4];
    const float* A_log   = (const float*)d_in[5];
    const float* norm_w  = (const float*)d_in[6];
    const float* W_out   = (const float*)d_in[7];
    float* out = (float*)d_out;

    float *qkvz, *qkv, *ba, *qhat, *khat, *oscan, *gated;
    float2* egbeta;
    cudaGetSymbolAddress((void**)&qkvz,   g_qkvz);
    cudaGetSymbolAddress((void**)&qkv,    g_qkv);
    cudaGetSymbolAddress((void**)&ba,     g_ba);
    cudaGetSymbolAddress((void**)&egbeta, g_egbeta);
    cudaGetSymbolAddress((void**)&qhat,   g_qhat);
    cudaGetSymbolAddress((void**)&khat,   g_khat);
    cudaGetSymbolAddress((void**)&oscan,  g_oscan);
    cudaGetSymbolAddress((void**)&gated,  g_gated);

    // 1. qkvz = h @ W_qkvz   [2048 x 12288], K=2048
    {
        dim3 grid(QKVZ_N / 128, T_SEQ / 128);
        sgemm128<<<grid, 256>>>(h_in, W_qkvz, qkvz, T_SEQ, QKVZ_N, HID);
    }
    // 2. ba = h @ W_ba  [2048 x 64]
    gemm_ba<<<T_SEQ, 64>>>(h_in, W_ba, ba);
    // 3. conv + silu over [q k v]
    conv_silu<<<(T_SEQ * CONV_DIM) / 256, 256>>>(qkvz, conv_w, qkv);
    // 4. gating
    gate_prep<<<(T_SEQ * NUM_V) / 256, 256>>>(ba, A_log, dt_bias, egbeta);
    // 5. l2norm q,k (+ q scale)
    l2norm_qk<<<(T_SEQ * 32) / 8, 256>>>(qkv, qhat, khat);
    // 6. gated delta scan
    gdn_scan<<<NUM_V * 16, 256>>>(qhat, khat, qkv, egbeta, oscan);
    // 7. rmsnorm + silu(z) gate
    rms_gate<<<(T_SEQ * NUM_V) / 8, 256>>>(oscan, qkvz, norm_w, gated);
    // 8. out = gated @ W_out  [2048 x 2048], K=4096
    {
        dim3 grid(HID / 128, T_SEQ / 128);
        sgemm128<<<grid, 256>>>(gated, W_out, out, T_SEQ, HID, VAL_DIM);
    }
}

// round 6
// speedup vs baseline: 1.5400x; 1.5400x over previous
#include <cuda_runtime.h>
#include <cuda_bf16.h>
#include <math.h>
#include <stdint.h>

// ---------------- problem constants ----------------
#define T_SEQ   2048
#define HID     2048
#define NUM_K   16
#define NUM_V   32
#define DK      128
#define DV      128
#define KEY_DIM 2048            // NUM_K*DK
#define VAL_DIM 4096            // NUM_V*DV
#define CONV_DIM 8192           // 2*KEY_DIM + VAL_DIM
#define QKVZ_N  12288           // 2*KEY_DIM + 2*VAL_DIM
#define QSCALE  0.08838834764831845f   // 128^-0.5

// ---------------- scratch (device globals; no cudaMalloc allowed) ----------------
__device__ float  g_qkvz  [T_SEQ * QKVZ_N];
__device__ float  g_qkv   [T_SEQ * CONV_DIM];
__device__ float  g_ba    [T_SEQ * 64];
__device__ float2 g_egbeta[T_SEQ * NUM_V];
__device__ float  g_qhat  [T_SEQ * KEY_DIM];
__device__ float  g_khat  [T_SEQ * KEY_DIM];
__device__ float  g_oscan [T_SEQ * VAL_DIM];
__device__ float  g_gated [T_SEQ * VAL_DIM];

// bf16 split operands for tensor-core GEMMs
__device__ __nv_bfloat16 g_Wq_hi[QKVZ_N * HID];    // W_qkvz^T  [N=12288][K=2048]
__device__ __nv_bfloat16 g_Wq_lo[QKVZ_N * HID];
__device__ __nv_bfloat16 g_Wo_hi[HID * VAL_DIM];   // W_out^T   [N=2048][K=4096]
__device__ __nv_bfloat16 g_Wo_lo[HID * VAL_DIM];
__device__ __nv_bfloat16 g_A_hi [T_SEQ * VAL_DIM];
__device__ __nv_bfloat16 g_A_lo [T_SEQ * VAL_DIM];

// ---------------- helpers ----------------
__device__ __forceinline__ float sigmoidf_(float x) { return 1.0f / (1.0f + __expf(-x)); }
__device__ __forceinline__ float siluf_(float x)    { return x * sigmoidf_(x); }

__device__ __forceinline__ uint32_t smem_to_u32(const void* p) {
    uint32_t a;
    asm("{ .reg .u64 t; cvta.to.shared.u64 t, %1; cvt.u32.u64 %0, t; }" : "=r"(a) : "l"(p));
    return a;
}

__device__ __forceinline__ void ldsm4(uint32_t& r0, uint32_t& r1, uint32_t& r2, uint32_t& r3,
                                      uint32_t addr) {
    asm volatile("ldmatrix.sync.aligned.m8n8.x4.shared.b16 {%0,%1,%2,%3}, [%4];"
                 : "=r"(r0), "=r"(r1), "=r"(r2), "=r"(r3) : "r"(addr));
}

__device__ __forceinline__ void mma16816(float* d, const uint32_t* a, const uint32_t* b) {
    asm volatile("mma.sync.aligned.m16n8k16.row.col.f32.bf16.bf16.f32 "
                 "{%0,%1,%2,%3}, {%4,%5,%6,%7}, {%8,%9}, {%0,%1,%2,%3};"
                 : "+f"(d[0]), "+f"(d[1]), "+f"(d[2]), "+f"(d[3])
                 : "r"(a[0]), "r"(a[1]), "r"(a[2]), "r"(a[3]), "r"(b[0]), "r"(b[1]));
}

// ---------------- prep: fp32 -> bf16 hi/lo split (row-major) ----------------
__global__ __launch_bounds__(256) void cvt_split(
    const float* __restrict__ x, __nv_bfloat16* __restrict__ hi,
    __nv_bfloat16* __restrict__ lo, int n4)
{
    int i = blockIdx.x * 256 + threadIdx.x;
    if (i >= n4) return;
    float4 v = ((const float4*)x)[i];
    __nv_bfloat16 h0 = __float2bfloat16(v.x);
    __nv_bfloat16 h1 = __float2bfloat16(v.y);
    __nv_bfloat16 h2 = __float2bfloat16(v.z);
    __nv_bfloat16 h3 = __float2bfloat16(v.w);
    __nv_bfloat16 l0 = __float2bfloat16(v.x - __bfloat162float(h0));
    __nv_bfloat16 l1 = __float2bfloat16(v.y - __bfloat162float(h1));
    __nv_bfloat16 l2 = __float2bfloat16(v.z - __bfloat162float(h2));
    __nv_bfloat16 l3 = __float2bfloat16(v.w - __bfloat162float(h3));
    union { __nv_bfloat162 b2[2]; uint2 u; } H, L;
    H.b2[0] = __halves2bfloat162(h0, h1); H.b2[1] = __halves2bfloat162(h2, h3);
    L.b2[0] = __halves2bfloat162(l0, l1); L.b2[1] = __halves2bfloat162(l2, l3);
    ((uint2*)hi)[i] = H.u;
    ((uint2*)lo)[i] = L.u;
}

// ---------------- prep: W [K][N] fp32 -> W^T [N][K] bf16 hi/lo ----------------
__global__ __launch_bounds__(256) void tr_split(
    const float* __restrict__ W, __nv_bfloat16* __restrict__ hi,
    __nv_bfloat16* __restrict__ lo, int K, int N)
{
    __shared__ float t[32][33];
    int n0 = blockIdx.x * 32, k0 = blockIdx.y * 32;
    int tx = threadIdx.x, ty = threadIdx.y;  // block (32,8)
#pragma unroll
    for (int j = 0; j < 4; ++j)
        t[ty + j * 8][tx] = W[(size_t)(k0 + ty + j * 8) * N + n0 + tx];
    __syncthreads();
#pragma unroll
    for (int j = 0; j < 4; ++j) {
        int n = ty + j * 8;
        float v = t[tx][n];
        __nv_bfloat16 h = __float2bfloat16(v);
        __nv_bfloat16 l = __float2bfloat16(v - __bfloat162float(h));
        size_t o = (size_t)(n0 + n) * K + k0 + tx;
        hi[o] = h;
        lo[o] = l;
    }
}

// ---------------- mma.sync GEMM: C[M,N] = A[M,K] @ B^T (B stored [N][K]) ----------------
// 128x128 CTA tile, BK=32, 8 warps (2x4), each warp 64x32 = 4x4 m16n8k16 tiles.
// 3-pass bf16 split: hi*hi + hi*lo + lo*hi. Padded smem rows (80B) for ldmatrix.
#define SSTR 80
#define STILE (128 * SSTR)

__global__ __launch_bounds__(256, 1) void gemm_tc(
    const __nv_bfloat16* __restrict__ Ahi, const __nv_bfloat16* __restrict__ Alo,
    const __nv_bfloat16* __restrict__ Bhi, const __nv_bfloat16* __restrict__ Blo,
    float* __restrict__ C, int N, int K)
{
    __shared__ __align__(16) char smem[4 * STILE];   // Ahi Alo Bhi Blo
    const uint32_t sb  = smem_to_u32(smem);
    const uint32_t sAh = sb;
    const uint32_t sAl = sb + STILE;
    const uint32_t sBh = sb + 2 * STILE;
    const uint32_t sBl = sb + 3 * STILE;

    const int tid  = threadIdx.x;
    const int wid  = tid >> 5;
    const int lane = tid & 31;
    const int bm   = blockIdx.x * 128;
    const int bn   = blockIdx.y * 128;
    const int wm   = (wid >> 2) * 64;     // warp row offset
    const int wn   = (wid & 3) * 32;      // warp col offset

    // staging coords: 512 uint4 per tile, 2 per thread
    const int r0q = tid * 2;              // idx 0
    const int row0 = r0q >> 2, quad0 = (r0q & 3);
    const int row1 = (r0q + 1) >> 2, quad1 = ((r0q + 1) & 3);

    const char* gAh = (const char*)(Ahi + (size_t)bm * K);
    const char* gAl = (const char*)(Alo + (size_t)bm * K);
    const char* gBh = (const char*)(Bhi + (size_t)bn * K);
    const char* gBl = (const char*)(Blo + (size_t)bn * K);
    const size_t gro0 = (size_t)row0 * K * 2 + quad0 * 16;
    const size_t gro1 = (size_t)row1 * K * 2 + quad1 * 16;
    const uint32_t so0 = row0 * SSTR + quad0 * 16;
    const uint32_t so1 = row1 * SSTR + quad1 * 16;

    float acc[16][4];
#pragma unroll
    for (int i = 0; i < 16; ++i)
#pragma unroll
        for (int j = 0; j < 4; ++j) acc[i][j] = 0.0f;

    // ldmatrix addresses (fixed per thread, add kstep byte offset)
    const uint32_t aoff = (lane & 15) * SSTR + ((lane >> 4) << 4);
    const uint32_t boff = ((lane & 7) + ((lane >> 4) << 3)) * SSTR + (((lane >> 3) & 1) << 4);

    uint4 pAh0, pAh1, pAl0, pAl1, pBh0, pBh1, pBl0, pBl1;
    pAh0 = *(const uint4*)(gAh + gro0); pAh1 = *(const uint4*)(gAh + gro1);
    pAl0 = *(const uint4*)(gAl + gro0); pAl1 = *(const uint4*)(gAl + gro1);
    pBh0 = *(const uint4*)(gBh + gro0); pBh1 = *(const uint4*)(gBh + gro1);
    pBl0 = *(const uint4*)(gBl + gro0); pBl1 = *(const uint4*)(gBl + gro1);

    const int nk = K >> 5;                 // BK = 32
    for (int kt = 0; kt < nk; ++kt) {
        *(uint4*)(smem + (sAh - sb) + so0) = pAh0;
        *(uint4*)(smem + (sAh - sb) + so1) = pAh1;
        *(uint4*)(smem + (sAl - sb) + so0) = pAl0;
        *(uint4*)(smem + (sAl - sb) + so1) = pAl1;
        *(uint4*)(smem + (sBh - sb) + so0) = pBh0;
        *(uint4*)(smem + (sBh - sb) + so1) = pBh1;
        *(uint4*)(smem + (sBl - sb) + so0) = pBl0;
        *(uint4*)(smem + (sBl - sb) + so1) = pBl1;
        __syncthreads();

        if (kt + 1 < nk) {
            size_t adv = (size_t)(kt + 1) * 64;   // 32 bf16 = 64 bytes
            pAh0 = *(const uint4*)(gAh + gro0 + adv); pAh1 = *(const uint4*)(gAh + gro1 + adv);
            pAl0 = *(const uint4*)(gAl + gro0 + adv); pAl1 = *(const uint4*)(gAl + gro1 + adv);
            pBh0 = *(const uint4*)(gBh + gro0 + adv); pBh1 = *(const uint4*)(gBh + gro1 + adv);
            pBl0 = *(const uint4*)(gBl + gro0 + adv); pBl1 = *(const uint4*)(gBl + gro1 + adv);
        }

#pragma unroll
        for (int ks = 0; ks < 2; ++ks) {
            const uint32_t kb = ks * 32;
            uint32_t ah[4][4], al[4][4], bh[4][2], bl[4][2];
#pragma unroll
            for (int mt = 0; mt < 4; ++mt) {
                uint32_t base = (wm + mt * 16) * SSTR + aoff + kb;
                ldsm4(ah[mt][0], ah[mt][1], ah[mt][2], ah[mt][3], sAh + base);
                ldsm4(al[mt][0], al[mt][1], al[mt][2], al[mt][3], sAl + base);
            }
#pragma unroll
            for (int pr = 0; pr < 2; ++pr) {
                uint32_t base = (wn + pr * 16) * SSTR + boff + kb;
                uint32_t r0, r1, r2, r3;
                ldsm4(r0, r1, r2, r3, sBh + base);
                bh[pr * 2][0] = r0; bh[pr * 2][1] = r1;
                bh[pr * 2 + 1][0] = r2; bh[pr * 2 + 1][1] = r3;
                ldsm4(r0, r1, r2, r3, sBl + base);
                bl[pr * 2][0] = r0; bl[pr * 2][1] = r1;
                bl[pr * 2 + 1][0] = r2; bl[pr * 2 + 1][1] = r3;
            }
#pragma unroll
            for (int mt = 0; mt < 4; ++mt)
#pragma unroll
                for (int nt = 0; nt < 4; ++nt)
                    mma16816(acc[mt * 4 + nt], ah[mt], bh[nt]);
#pragma unroll
            for (int mt = 0; mt < 4; ++mt)
#pragma unroll
                for (int nt = 0; nt < 4; ++nt)
                    mma16816(acc[mt * 4 + nt], ah[mt], bl[nt]);
#pragma unroll
            for (int mt = 0; mt < 4; ++mt)
#pragma unroll
                for (int nt = 0; nt < 4; ++nt)
                    mma16816(acc[mt * 4 + nt], al[mt], bh[nt]);
        }
        __syncthreads();
    }

    // epilogue: d0,d1 -> (row g, col tg*2, +1); d2,d3 -> row g+8
    const int g  = lane >> 2;
    const int tg = lane & 3;
#pragma unroll
    for (int mt = 0; mt < 4; ++mt) {
#pragma unroll
        for (int nt = 0; nt < 4; ++nt) {
            const float* d = acc[mt * 4 + nt];
            size_t r = (size_t)(bm + wm + mt * 16 + g) * N + bn + wn + nt * 8 + tg * 2;
            C[r]     = d[0];
            C[r + 1] = d[1];
            C[r + 8 * (size_t)N]     = d[2];
            C[r + 8 * (size_t)N + 1] = d[3];
        }
    }
}

// ---------------- small GEMM: ba = h @ W_ba ----------------
__global__ __launch_bounds__(64) void gemm_ba(
    const float* __restrict__ A, const float* __restrict__ B, float* __restrict__ C)
{
    __shared__ float hrow[HID];
    const int row = blockIdx.x;
    const int tid = threadIdx.x;
    for (int i = tid; i < HID; i += 64) hrow[i] = A[(size_t)row * HID + i];
    __syncthreads();
    float acc = 0.0f;
#pragma unroll 8
    for (int k = 0; k < HID; ++k)
        acc = fmaf(hrow[k], B[(size_t)k * 64 + tid], acc);
    C[(size_t)row * 64 + tid] = acc;
}

// ---------------- causal depthwise conv (K=4) + SiLU ----------------
__global__ __launch_bounds__(256) void conv_silu(
    const float* __restrict__ qkvz, const float* __restrict__ conv_w,
    float* __restrict__ out)
{
    int idx = blockIdx.x * blockDim.x + threadIdx.x;
    if (idx >= T_SEQ * CONV_DIM) return;
    int t = idx >> 13;
    int c = idx & (CONV_DIM - 1);
    const float* w = conv_w + c * 4;
    float acc = w[3] * qkvz[(size_t)t * QKVZ_N + c];
    if (t >= 1) acc = fmaf(w[2], qkvz[(size_t)(t - 1) * QKVZ_N + c], acc);
    if (t >= 2) acc = fmaf(w[1], qkvz[(size_t)(t - 2) * QKVZ_N + c], acc);
    if (t >= 3) acc = fmaf(w[0], qkvz[(size_t)(t - 3) * QKVZ_N + c], acc);
    out[idx] = siluf_(acc);
}

// ---------------- gating ----------------
__global__ __launch_bounds__(256) void gate_prep(
    const float* __restrict__ ba, const float* __restrict__ A_log,
    const float* __restrict__ dt_bias, float2* __restrict__ egbeta)
{
    int i = blockIdx.x * blockDim.x + threadIdx.x;
    if (i >= T_SEQ * NUM_V) return;
    int t = i >> 5;
    int h = i & 31;
    float b = ba[(size_t)t * 64 + h];
    float a = ba[(size_t)t * 64 + 32 + h];
    float x = a + dt_bias[h];
    float sp = (x > 20.0f) ? x : log1pf(expf(x));
    float g = -expf(A_log[h]) * sp;
    egbeta[i] = make_float2(expf(g), sigmoidf_(b));
}

// ---------------- l2norm of q and k; scale folded into q ----------------
__global__ __launch_bounds__(256) void l2norm_qk(
    const float* __restrict__ qkv, float* __restrict__ qhat, float* __restrict__ khat)
{
    int gid  = blockIdx.x * 8 + (threadIdx.x >> 5);
    int lane = threadIdx.x & 31;
    int t   = gid >> 5;
    int sub = gid & 31;
    int kh  = sub & 15;
    int isK = sub >> 4;
    const float* src = qkv + (size_t)t * CONV_DIM + isK * KEY_DIM + kh * DK;
    float4 x = *(const float4*)(src + lane * 4);
    float s = x.x * x.x + x.y * x.y + x.z * x.z + x.w * x.w;
#pragma unroll
    for (int off = 16; off > 0; off >>= 1) s += __shfl_xor_sync(0xffffffffu, s, off);
    float r = rsqrtf(s + 1e-6f);
    if (!isK) r *= QSCALE;
    float* dst = (isK ? khat : qhat) + (size_t)t * KEY_DIM + kh * DK;
    *(float4*)(dst + lane * 4) = make_float4(x.x * r, x.y * r, x.z * r, x.w * r);
}

// ---------------- gated delta scan: one warp per (head, v-column) ----------------
__global__ __launch_bounds__(256) void gdn_scan(
    const float* __restrict__ qhat, const float* __restrict__ khat,
    const float* __restrict__ qkv, const float2* __restrict__ egbeta,
    float* __restrict__ o)
{
    const int warp = threadIdx.x >> 5;
    const int lane = threadIdx.x & 31;
    const int h   = blockIdx.x >> 4;
    const int col = ((blockIdx.x & 15) << 3) + warp;
    const int kh  = h >> 1;

    const float4* kp = (const float4*)(khat + kh * DK) + lane;
    const float4* qp = (const float4*)(qhat + kh * DK) + lane;
    const float*  vp = qkv + 2 * KEY_DIM + h * DV + col;
    const float2* ep = egbeta + h;
    float*        op = o + h * DV + col;

    float S0 = 0.f, S1 = 0.f, S2 = 0.f, S3 = 0.f;

    float4 kk = *kp, qq = *qp;
    float  vt = *vp;
    float2 eb = *ep;

    for (int t = 0; t < T_SEQ; ++t) {
        float4 kk_n, qq_n; float vt_n; float2 eb_n;
        if (t < T_SEQ - 1) {
            kp += KEY_DIM / 4; qp += KEY_DIM / 4; vp += CONV_DIM; ep += NUM_V;
            kk_n = *kp; qq_n = *qp; vt_n = *vp; eb_n = *ep;
        } else {
            kk_n = kk; qq_n = qq; vt_n = vt; eb_n = eb;
        }

        float dk  = kk.x * S0 + kk.y * S1 + kk.z * S2 + kk.w * S3;
        float dq  = qq.x * S0 + qq.y * S1 + qq.z * S2 + qq.w * S3;
        float dqk = qq.x * kk.x + qq.y * kk.y + qq.z * kk.z + qq.w * kk.w;
#pragma unroll
        for (int off = 16; off > 0; off >>= 1) {
            dk  += __shfl_xor_sync(0xffffffffu, dk,  off);
            dq  += __shfl_xor_sync(0xffffffffu, dq,  off);
            dqk += __shfl_xor_sync(0xffffffffu, dqk, off);
        }
        const float eg = eb.x, beta = eb.y;
        const float kv    = eg * dk;
        const float delta = (vt - kv) * beta;
        const float ot    = fmaf(eg, dq, dqk * delta);
        S0 = fmaf(S0, eg, kk.x * delta);
        S1 = fmaf(S1, eg, kk.y * delta);
        S2 = fmaf(S2, eg, kk.z * delta);
        S3 = fmaf(S3, eg, kk.w * delta);
        if (lane == 0) *op = ot;
        op += VAL_DIM;
        kk = kk_n; qq = qq_n; vt = vt_n; eb = eb_n;
    }
}

// ---------------- RMSNorm * norm_w * silu(z) ----------------
__global__ __launch_bounds__(256) void rms_gate(
    const float* __restrict__ o, const float* __restrict__ qkvz,
    const float* __restrict__ norm_w, float* __restrict__ gated)
{
    int gid  = blockIdx.x * 8 + (threadIdx.x >> 5);
    int lane = threadIdx.x & 31;
    int t = gid >> 5;
    int h = gid & 31;
    const float* orow = o + (size_t)t * VAL_DIM + h * DV;
    float4 x = *(const float4*)(orow + lane * 4);
    float s = x.x * x.x + x.y * x.y + x.z * x.z + x.w * x.w;
#pragma unroll
    for (int off = 16; off > 0; off >>= 1) s += __shfl_xor_sync(0xffffffffu, s, off);
    float r = rsqrtf(s * (1.0f / DV) + 1e-6f);
    float4 z  = *(const float4*)(qkvz + (size_t)t * QKVZ_N + 2 * KEY_DIM + VAL_DIM + h * DV + lane * 4);
    float4 nw = *(const float4*)(norm_w + lane * 4);
    float4 y;
    y.x = x.x * r * nw.x * siluf_(z.x);
    y.y = x.y * r * nw.y * siluf_(z.y);
    y.z = x.z * r * nw.z * siluf_(z.z);
    y.w = x.w * r * nw.w * siluf_(z.w);
    *(float4*)(gated + (size_t)t * VAL_DIM + h * DV + lane * 4) = y;
}

// ---------------- launch ----------------
extern "C" void kernel_launch(void* const* d_in, const int* in_sizes, int n_in,
                              void* d_out, int out_size)
{
    const float* h_in    = (const float*)d_in[0];
    const float* W_qkvz  = (const float*)d_in[1];
    const float* W_ba    = (const float*)d_in[2];
    const float* conv_w  = (const float*)d_in[3];
    const float* dt_bias = (const float*)d_in[4];
    const float* A_log   = (const float*)d_in[5];
    const float* norm_w  = (const float*)d_in[6];
    const float* W_out   = (const float*)d_in[7];
    float* out = (float*)d_out;

    float *qkvz, *qkv, *ba, *qhat, *khat, *oscan, *gated;
    float2* egbeta;
    __nv_bfloat16 *Wq_hi, *Wq_lo, *Wo_hi, *Wo_lo, *A_hi, *A_lo;
    cudaGetSymbolAddress((void**)&qkvz,   g_qkvz);
    cudaGetSymbolAddress((void**)&qkv,    g_qkv);
    cudaGetSymbolAddress((void**)&ba,     g_ba);
    cudaGetSymbolAddress((void**)&egbeta, g_egbeta);
    cudaGetSymbolAddress((void**)&qhat,   g_qhat);
    cudaGetSymbolAddress((void**)&khat,   g_khat);
    cudaGetSymbolAddress((void**)&oscan,  g_oscan);
    cudaGetSymbolAddress((void**)&gated,  g_gated);
    cudaGetSymbolAddress((void**)&Wq_hi,  g_Wq_hi);
    cudaGetSymbolAddress((void**)&Wq_lo,  g_Wq_lo);
    cudaGetSymbolAddress((void**)&Wo_hi,  g_Wo_hi);
    cudaGetSymbolAddress((void**)&Wo_lo,  g_Wo_lo);
    cudaGetSymbolAddress((void**)&A_hi,   g_A_hi);
    cudaGetSymbolAddress((void**)&A_lo,   g_A_lo);

    // prep: transpose+split weights, split activations
    {
        dim3 blk(32, 8);
        tr_split<<<dim3(QKVZ_N / 32, HID / 32), blk>>>(W_qkvz, Wq_hi, Wq_lo, HID, QKVZ_N);
        tr_split<<<dim3(HID / 32, VAL_DIM / 32), blk>>>(W_out, Wo_hi, Wo_lo, VAL_DIM, HID);
    }
    cvt_split<<<(T_SEQ * HID / 4 + 255) / 256, 256>>>(h_in, A_hi, A_lo, T_SEQ * HID / 4);

    // GEMM1: qkvz = h @ W_qkvz   [2048 x 12288], K=2048
    gemm_tc<<<dim3(T_SEQ / 128, QKVZ_N / 128), 256>>>(A_hi, A_lo, Wq_hi, Wq_lo, qkvz, QKVZ_N, HID);

    gemm_ba<<<T_SEQ, 64>>>(h_in, W_ba, ba);
    conv_silu<<<(T_SEQ * CONV_DIM) / 256, 256>>>(qkvz, conv_w, qkv);
    gate_prep<<<(T_SEQ * NUM_V) / 256, 256>>>(ba, A_log, dt_bias, egbeta);
    l2norm_qk<<<(T_SEQ * 32) / 8, 256>>>(qkv, qhat, khat);
    gdn_scan<<<NUM_V * 16, 256>>>(qhat, khat, qkv, egbeta, oscan);
    rms_gate<<<(T_SEQ * NUM_V) / 8, 256>>>(oscan, qkvz, norm_w, gated);

    // GEMM2: out = gated @ W_out  [2048 x 2048], K=4096
    cvt_split<<<(T_SEQ * VAL_DIM / 4 + 255) / 256, 256>>>(gated, A_hi, A_lo, T_SEQ * VAL_DIM / 4);
    gemm_tc<<<dim3(T_SEQ / 128, HID / 128), 256>>>(A_hi, A_lo, Wo_hi, Wo_lo, out, HID, VAL_DIM);
}

// round 7
// speedup vs baseline: 1.6344x; 1.0613x over previous
#include <cuda_runtime.h>
#include <cuda_bf16.h>
#include <math.h>
#include <stdint.h>

// ---------------- problem constants ----------------
#define T_SEQ   2048
#define HID     2048
#define NUM_K   16
#define NUM_V   32
#define DK      128
#define DV      128
#define KEY_DIM 2048
#define VAL_DIM 4096
#define CONV_DIM 8192
#define QKVZ_N  12288
#define QSCALE  0.08838834764831845f

// ---------------- scratch ----------------
__device__ float  g_qkvz  [T_SEQ * QKVZ_N];
__device__ float  g_qkv   [T_SEQ * CONV_DIM];
__device__ float  g_ba    [T_SEQ * 64];
__device__ float2 g_egbeta[T_SEQ * NUM_V];
__device__ float  g_qhat  [T_SEQ * KEY_DIM];
__device__ float  g_khat  [T_SEQ * KEY_DIM];
__device__ float  g_qkdot [T_SEQ * NUM_K];
__device__ float  g_oscan [T_SEQ * VAL_DIM];

__device__ __nv_bfloat16 g_Wq_hi[QKVZ_N * HID];
__device__ __nv_bfloat16 g_Wq_lo[QKVZ_N * HID];
__device__ __nv_bfloat16 g_Wo_hi[HID * VAL_DIM];
__device__ __nv_bfloat16 g_Wo_lo[HID * VAL_DIM];
__device__ __nv_bfloat16 g_A_hi [T_SEQ * VAL_DIM];
__device__ __nv_bfloat16 g_A_lo [T_SEQ * VAL_DIM];

// ---------------- helpers ----------------
__device__ __forceinline__ float sigmoidf_(float x) { return 1.0f / (1.0f + __expf(-x)); }
__device__ __forceinline__ float siluf_(float x)    { return x * sigmoidf_(x); }

__device__ __forceinline__ uint32_t smem_to_u32(const void* p) {
    uint32_t a;
    asm("{ .reg .u64 t; cvta.to.shared.u64 t, %1; cvt.u32.u64 %0, t; }" : "=r"(a) : "l"(p));
    return a;
}
__device__ __forceinline__ void ldsm4(uint32_t& r0, uint32_t& r1, uint32_t& r2, uint32_t& r3,
                                      uint32_t addr) {
    asm volatile("ldmatrix.sync.aligned.m8n8.x4.shared.b16 {%0,%1,%2,%3}, [%4];"
                 : "=r"(r0), "=r"(r1), "=r"(r2), "=r"(r3) : "r"(addr));
}
__device__ __forceinline__ void mma16816(float* d, const uint32_t* a, const uint32_t* b) {
    asm volatile("mma.sync.aligned.m16n8k16.row.col.f32.bf16.bf16.f32 "
                 "{%0,%1,%2,%3}, {%4,%5,%6,%7}, {%8,%9}, {%0,%1,%2,%3};"
                 : "+f"(d[0]), "+f"(d[1]), "+f"(d[2]), "+f"(d[3])
                 : "r"(a[0]), "r"(a[1]), "r"(a[2]), "r"(a[3]), "r"(b[0]), "r"(b[1]));
}

// ---------------- prep: fp32 -> bf16 hi/lo split ----------------
__global__ __launch_bounds__(256) void cvt_split(
    const float* __restrict__ x, __nv_bfloat16* __restrict__ hi,
    __nv_bfloat16* __restrict__ lo, int n4)
{
    int i = blockIdx.x * 256 + threadIdx.x;
    if (i >= n4) return;
    float4 v = ((const float4*)x)[i];
    __nv_bfloat16 h0 = __float2bfloat16(v.x);
    __nv_bfloat16 h1 = __float2bfloat16(v.y);
    __nv_bfloat16 h2 = __float2bfloat16(v.z);
    __nv_bfloat16 h3 = __float2bfloat16(v.w);
    __nv_bfloat16 l0 = __float2bfloat16(v.x - __bfloat162float(h0));
    __nv_bfloat16 l1 = __float2bfloat16(v.y - __bfloat162float(h1));
    __nv_bfloat16 l2 = __float2bfloat16(v.z - __bfloat162float(h2));
    __nv_bfloat16 l3 = __float2bfloat16(v.w - __bfloat162float(h3));
    union { __nv_bfloat162 b2[2]; uint2 u; } H, L;
    H.b2[0] = __halves2bfloat162(h0, h1); H.b2[1] = __halves2bfloat162(h2, h3);
    L.b2[0] = __halves2bfloat162(l0, l1); L.b2[1] = __halves2bfloat162(l2, l3);
    ((uint2*)hi)[i] = H.u;
    ((uint2*)lo)[i] = L.u;
}

// ---------------- prep: W [K][N] -> W^T [N][K] bf16 hi/lo ----------------
__global__ __launch_bounds__(256) void tr_split(
    const float* __restrict__ W, __nv_bfloat16* __restrict__ hi,
    __nv_bfloat16* __restrict__ lo, int K, int N)
{
    __shared__ float t[32][33];
    int n0 = blockIdx.x * 32, k0 = blockIdx.y * 32;
    int tx = threadIdx.x, ty = threadIdx.y;
#pragma unroll
    for (int j = 0; j < 4; ++j)
        t[ty + j * 8][tx] = W[(size_t)(k0 + ty + j * 8) * N + n0 + tx];
    __syncthreads();
#pragma unroll
    for (int j = 0; j < 4; ++j) {
        int n = ty + j * 8;
        float v = t[tx][n];
        __nv_bfloat16 h = __float2bfloat16(v);
        __nv_bfloat16 l = __float2bfloat16(v - __bfloat162float(h));
        size_t o = (size_t)(n0 + n) * K + k0 + tx;
        hi[o] = h;
        lo[o] = l;
    }
}

// ---------------- mma.sync GEMM v2: 128x256 CTA, 64x64 warp tiles, cp.async 3-stage ----------------
#define SSTR   80
#define SZ_A   (128 * SSTR)
#define SZ_B   (256 * SSTR)
#define BUF_SZ (2 * SZ_A + 2 * SZ_B)    // Ahi Alo Bhi Blo = 61440
#define GT_SMEM (3 * BUF_SZ)            // 184320

template<int ITERS>
__device__ __forceinline__ void cpa_stage(uint32_t sdst, const char* g, int Kb, int tid) {
#pragma unroll
    for (int i = 0; i < ITERS; ++i) {
        int idx = tid + i * 256;
        int row = idx >> 2;
        int q   = (idx & 3) << 4;
        uint32_t d = sdst + row * SSTR + q;
        const char* s = g + (size_t)row * Kb + q;
        asm volatile("cp.async.cg.shared.global [%0], [%1], 16;" :: "r"(d), "l"(s));
    }
}

__global__ __launch_bounds__(256, 1) void gemm_tc(
    const __nv_bfloat16* __restrict__ Ahi, const __nv_bfloat16* __restrict__ Alo,
    const __nv_bfloat16* __restrict__ Bhi, const __nv_bfloat16* __restrict__ Blo,
    float* __restrict__ C, int N, int K)
{
    extern __shared__ __align__(128) char smem[];
    const uint32_t sb = smem_to_u32(smem);

    const int tid  = threadIdx.x;
    const int wid  = tid >> 5;
    const int lane = tid & 31;
    const int bm   = blockIdx.x * 128;
    const int bn   = blockIdx.y * 256;
    const int wm   = (wid >> 2) * 64;
    const int wn   = (wid & 3) * 64;
    const int Kb   = K * 2;

    const char* gAh = (const char*)(Ahi + (size_t)bm * K);
    const char* gAl = (const char*)(Alo + (size_t)bm * K);
    const char* gBh = (const char*)(Bhi + (size_t)bn * K);
    const char* gBl = (const char*)(Blo + (size_t)bn * K);

    float acc[4][8][4];
#pragma unroll
    for (int i = 0; i < 4; ++i)
#pragma unroll
        for (int j = 0; j < 8; ++j)
#pragma unroll
            for (int r = 0; r < 4; ++r) acc[i][j][r] = 0.0f;

    const uint32_t aoff = (lane & 15) * SSTR + ((lane >> 4) << 4);
    const uint32_t boff = ((lane & 7) + ((lane >> 4) << 3)) * SSTR + (((lane >> 3) & 1) << 4);

    const int nk = K >> 5;

    // prologue: stage chunks 0 and 1
#pragma unroll
    for (int p = 0; p < 2; ++p) {
        uint32_t sbuf = sb + p * BUF_SZ;
        size_t ko = (size_t)p * 64;
        cpa_stage<2>(sbuf,                    gAh + ko, Kb, tid);
        cpa_stage<2>(sbuf + SZ_A,             gAl + ko, Kb, tid);
        cpa_stage<4>(sbuf + 2 * SZ_A,         gBh + ko, Kb, tid);
        cpa_stage<4>(sbuf + 2 * SZ_A + SZ_B,  gBl + ko, Kb, tid);
        asm volatile("cp.async.commit_group;");
    }

    int buf = 0;
    for (int kt = 0; kt < nk; ++kt) {
        asm volatile("cp.async.wait_group 1;");
        __syncthreads();

        // stage kt+2 into the third buffer (or commit empty group to keep counts)
        if (kt + 2 < nk) {
            int nb = (buf + 2) % 3;
            uint32_t sbuf = sb + nb * BUF_SZ;
            size_t ko = (size_t)(kt + 2) * 64;
            cpa_stage<2>(sbuf,                    gAh + ko, Kb, tid);
            cpa_stage<2>(sbuf + SZ_A,             gAl + ko, Kb, tid);
            cpa_stage<4>(sbuf + 2 * SZ_A,         gBh + ko, Kb, tid);
            cpa_stage<4>(sbuf + 2 * SZ_A + SZ_B,  gBl + ko, Kb, tid);
        }
        asm volatile("cp.async.commit_group;");

        const uint32_t sAh = sb + buf * BUF_SZ;
        const uint32_t sAl = sAh + SZ_A;
        const uint32_t sBh = sAh + 2 * SZ_A;
        const uint32_t sBl = sBh + SZ_B;

#pragma unroll
        for (int ks = 0; ks < 2; ++ks) {
            const uint32_t kb = ks * 32;
            uint32_t ah[4][4], al[4][4];
#pragma unroll
            for (int mt = 0; mt < 4; ++mt) {
                uint32_t base = (wm + mt * 16) * SSTR + aoff + kb;
                ldsm4(ah[mt][0], ah[mt][1], ah[mt][2], ah[mt][3], sAh + base);
                ldsm4(al[mt][0], al[mt][1], al[mt][2], al[mt][3], sAl + base);
            }
#pragma unroll
            for (int pr = 0; pr < 4; ++pr) {
                uint32_t bbase = (wn + pr * 16) * SSTR + boff + kb;
                uint32_t h0, h1, h2, h3, l0, l1, l2, l3;
                ldsm4(h0, h1, h2, h3, sBh + bbase);
                ldsm4(l0, l1, l2, l3, sBl + bbase);
                uint32_t b0[2] = {h0, h1}, b1[2] = {h2, h3};
                uint32_t c0[2] = {l0, l1}, c1[2] = {l2, l3};
#pragma unroll
                for (int mt = 0; mt < 4; ++mt) {
                    mma16816(acc[mt][2 * pr],     ah[mt], b0);
                    mma16816(acc[mt][2 * pr + 1], ah[mt], b1);
                    mma16816(acc[mt][2 * pr],     ah[mt], c0);
                    mma16816(acc[mt][2 * pr + 1], ah[mt], c1);
                    mma16816(acc[mt][2 * pr],     al[mt], b0);
                    mma16816(acc[mt][2 * pr + 1], al[mt], b1);
                }
            }
        }
        buf = (buf + 1) % 3;
        __syncthreads();
    }

    const int g  = lane >> 2;
    const int tg = lane & 3;
#pragma unroll
    for (int mt = 0; mt < 4; ++mt) {
#pragma unroll
        for (int nt = 0; nt < 8; ++nt) {
            const float* d = acc[mt][nt];
            size_t r = (size_t)(bm + wm + mt * 16 + g) * N + bn + wn + nt * 8 + tg * 2;
            C[r]     = d[0];
            C[r + 1] = d[1];
            C[r + 8 * (size_t)N]     = d[2];
            C[r + 8 * (size_t)N + 1] = d[3];
        }
    }
}

// ---------------- tiled small GEMM: ba = h @ W_ba (2048x64, K=2048) ----------------
__global__ __launch_bounds__(256) void gemm_ba(
    const float* __restrict__ A, const float* __restrict__ B, float* __restrict__ C)
{
    __shared__ float sh[64][65];
    __shared__ float sB[64][65];
    const int tid = threadIdx.x;
    const int col = tid & 63;
    const int rg  = tid >> 6;          // 4 groups x 16 rows
    const int br  = blockIdx.x * 64;

    float acc[16];
#pragma unroll
    for (int r = 0; r < 16; ++r) acc[r] = 0.0f;

    for (int kt = 0; kt < HID / 64; ++kt) {
#pragma unroll
        for (int i = 0; i < 16; ++i) {
            int idx = tid + i * 256;
            int row = idx >> 6, kk = idx & 63;
            sh[row][kk] = A[(size_t)(br + row) * HID + kt * 64 + kk];
            sB[row][kk] = B[(size_t)(kt * 64 + row) * 64 + kk];
        }
        __syncthreads();
#pragma unroll 16
        for (int kk = 0; kk < 64; ++kk) {
            float b = sB[kk][col];
#pragma unroll
            for (int r = 0; r < 16; ++r)
                acc[r] = fmaf(sh[rg * 16 + r][kk], b, acc[r]);
        }
        __syncthreads();
    }
#pragma unroll
    for (int r = 0; r < 16; ++r)
        C[(size_t)(br + rg * 16 + r) * 64 + col] = acc[r];
}

// ---------------- causal depthwise conv (K=4) + SiLU, 4 t per thread ----------------
__global__ __launch_bounds__(256) void conv_silu(
    const float* __restrict__ qkvz, const float* __restrict__ conv_w,
    float* __restrict__ out)
{
    int idx = blockIdx.x * blockDim.x + threadIdx.x;   // (T/4)*CONV_DIM
    if (idx >= (T_SEQ / 4) * CONV_DIM) return;
    int tq = idx >> 13;
    int c  = idx & (CONV_DIM - 1);
    int t0 = tq * 4;
    const float* w = conv_w + c * 4;
    float xv[7];
#pragma unroll
    for (int j = 0; j < 7; ++j) {
        int tt = t0 - 3 + j;
        xv[j] = (tt >= 0) ? qkvz[(size_t)tt * QKVZ_N + c] : 0.0f;
    }
#pragma unroll
    for (int i = 0; i < 4; ++i) {
        float a = w[0] * xv[i];
        a = fmaf(w[1], xv[i + 1], a);
        a = fmaf(w[2], xv[i + 2], a);
        a = fmaf(w[3], xv[i + 3], a);
        out[(size_t)(t0 + i) * CONV_DIM + c] = siluf_(a);
    }
}

// ---------------- gating ----------------
__global__ __launch_bounds__(256) void gate_prep(
    const float* __restrict__ ba, const float* __restrict__ A_log,
    const float* __restrict__ dt_bias, float2* __restrict__ egbeta)
{
    int i = blockIdx.x * blockDim.x + threadIdx.x;
    if (i >= T_SEQ * NUM_V) return;
    int t = i >> 5;
    int h = i & 31;
    float b = ba[(size_t)t * 64 + h];
    float a = ba[(size_t)t * 64 + 32 + h];
    float x = a + dt_bias[h];
    float sp = (x > 20.0f) ? x : log1pf(expf(x));
    float g = -expf(A_log[h]) * sp;
    egbeta[i] = make_float2(expf(g), sigmoidf_(b));
}

// ---------------- l2norm of q and k; scale folded into q ----------------
__global__ __launch_bounds__(256) void l2norm_qk(
    const float* __restrict__ qkv, float* __restrict__ qhat, float* __restrict__ khat)
{
    int gid  = blockIdx.x * 8 + (threadIdx.x >> 5);
    int lane = threadIdx.x & 31;
    int t   = gid >> 5;
    int sub = gid & 31;
    int kh  = sub & 15;
    int isK = sub >> 4;
    const float* src = qkv + (size_t)t * CONV_DIM + isK * KEY_DIM + kh * DK;
    float4 x = *(const float4*)(src + lane * 4);
    float s = x.x * x.x + x.y * x.y + x.z * x.z + x.w * x.w;
#pragma unroll
    for (int off = 16; off > 0; off >>= 1) s += __shfl_xor_sync(0xffffffffu, s, off);
    float r = rsqrtf(s + 1e-6f);
    if (!isK) r *= QSCALE;
    float* dst = (isK ? khat : qhat) + (size_t)t * KEY_DIM + kh * DK;
    *(float4*)(dst + lane * 4) = make_float4(x.x * r, x.y * r, x.z * r, x.w * r);
}

// ---------------- qk dot: dqk[t][kh] = qhat . khat ----------------
__global__ __launch_bounds__(256) void qk_dot(
    const float* __restrict__ qhat, const float* __restrict__ khat,
    float* __restrict__ qk)
{
    int gid  = blockIdx.x * 8 + (threadIdx.x >> 5);   // over T_SEQ*NUM_K
    int lane = threadIdx.x & 31;
    int t  = gid >> 4;
    int kh = gid & 15;
    const float4* qp = (const float4*)(qhat + (size_t)t * KEY_DIM + kh * DK) + lane;
    const float4* kp = (const float4*)(khat + (size_t)t * KEY_DIM + kh * DK) + lane;
    float4 q = *qp, k = *kp;
    float s = q.x * k.x + q.y * k.y + q.z * k.z + q.w * k.w;
#pragma unroll
    for (int off = 16; off > 0; off >>= 1) s += __shfl_xor_sync(0xffffffffu, s, off);
    if (lane == 0) qk[t * NUM_K + kh] = s;
}

// ---------------- gated delta scan: one warp per (head, v-column) ----------------
__global__ __launch_bounds__(256) void gdn_scan(
    const float* __restrict__ qhat, const float* __restrict__ khat,
    const float* __restrict__ qkv, const float2* __restrict__ egbeta,
    const float* __restrict__ qk, float* __restrict__ o)
{
    const int warp = threadIdx.x >> 5;
    const int lane = threadIdx.x & 31;
    const int h   = blockIdx.x >> 4;
    const int col = ((blockIdx.x & 15) << 3) + warp;
    const int kh  = h >> 1;

    const float4* kp = (const float4*)(khat + kh * DK) + lane;
    const float4* qp = (const float4*)(qhat + kh * DK) + lane;
    const float*  vp = qkv + 2 * KEY_DIM + h * DV + col;
    const float2* ep = egbeta + h;
    const float*  xp = qk + kh;
    float*        op = o + h * DV + col;

    float S0 = 0.f, S1 = 0.f, S2 = 0.f, S3 = 0.f;

    float4 kk = *kp, qq = *qp;
    float  vt = *vp;
    float2 eb = *ep;
    float  xq = *xp;

    for (int t = 0; t < T_SEQ; ++t) {
        float4 kk_n, qq_n; float vt_n, xq_n; float2 eb_n;
        if (t < T_SEQ - 1) {
            kp += KEY_DIM / 4; qp += KEY_DIM / 4; vp += CONV_DIM; ep += NUM_V; xp += NUM_K;
            kk_n = *kp; qq_n = *qp; vt_n = *vp; eb_n = *ep; xq_n = *xp;
        } else {
            kk_n = kk; qq_n = qq; vt_n = vt; eb_n = eb; xq_n = xq;
        }

        float dk = kk.x * S0 + kk.y * S1 + kk.z * S2 + kk.w * S3;
        float dq = qq.x * S0 + qq.y * S1 + qq.z * S2 + qq.w * S3;
#pragma unroll
        for (int off = 16; off > 0; off >>= 1) {
            dk += __shfl_xor_sync(0xffffffffu, dk, off);
            dq += __shfl_xor_sync(0xffffffffu, dq, off);
        }
        const float eg = eb.x, beta = eb.y;
        const float delta = (vt - eg * dk) * beta;
        const float ot    = fmaf(eg, dq, xq * delta);
        S0 = fmaf(S0, eg, kk.x * delta);
        S1 = fmaf(S1, eg, kk.y * delta);
        S2 = fmaf(S2, eg, kk.z * delta);
        S3 = fmaf(S3, eg, kk.w * delta);
        if (lane == 0) *op = ot;
        op += VAL_DIM;
        kk = kk_n; qq = qq_n; vt = vt_n; eb = eb_n; xq = xq_n;
    }
}

// ---------------- RMSNorm * norm_w * silu(z), write bf16 hi/lo directly ----------------
__global__ __launch_bounds__(256) void rms_gate_split(
    const float* __restrict__ o, const float* __restrict__ qkvz,
    const float* __restrict__ norm_w,
    __nv_bfloat16* __restrict__ hi, __nv_bfloat16* __restrict__ lo)
{
    int gid  = blockIdx.x * 8 + (threadIdx.x >> 5);
    int lane = threadIdx.x & 31;
    int t = gid >> 5;
    int h = gid & 31;
    const float* orow = o + (size_t)t * VAL_DIM + h * DV;
    float4 x = *(const float4*)(orow + lane * 4);
    float s = x.x * x.x + x.y * x.y + x.z * x.z + x.w * x.w;
#pragma unroll
    for (int off = 16; off > 0; off >>= 1) s += __shfl_xor_sync(0xffffffffu, s, off);
    float r = rsqrtf(s * (1.0f / DV) + 1e-6f);
    float4 z  = *(const float4*)(qkvz + (size_t)t * QKVZ_N + 2 * KEY_DIM + VAL_DIM + h * DV + lane * 4);
    float4 nw = *(const float4*)(norm_w + lane * 4);
    float4 y;
    y.x = x.x * r * nw.x * siluf_(z.x);
    y.y = x.y * r * nw.y * siluf_(z.y);
    y.z = x.z * r * nw.z * siluf_(z.z);
    y.w = x.w * r * nw.w * siluf_(z.w);
    __nv_bfloat16 h0 = __float2bfloat16(y.x), h1 = __float2bfloat16(y.y);
    __nv_bfloat16 h2 = __float2bfloat16(y.z), h3 = __float2bfloat16(y.w);
    __nv_bfloat16 l0 = __float2bfloat16(y.x - __bfloat162float(h0));
    __nv_bfloat16 l1 = __float2bfloat16(y.y - __bfloat162float(h1));
    __nv_bfloat16 l2 = __float2bfloat16(y.z - __bfloat162float(h2));
    __nv_bfloat16 l3 = __float2bfloat16(y.w - __bfloat162float(h3));
    union { __nv_bfloat162 b2[2]; uint2 u; } H, L;
    H.b2[0] = __halves2bfloat162(h0, h1); H.b2[1] = __halves2bfloat162(h2, h3);
    L.b2[0] = __halves2bfloat162(l0, l1); L.b2[1] = __halves2bfloat162(l2, l3);
    int i4 = (t * VAL_DIM + h * DV) / 4 + lane;
    ((uint2*)hi)[i4] = H.u;
    ((uint2*)lo)[i4] = L.u;
}

// ---------------- launch ----------------
extern "C" void kernel_launch(void* const* d_in, const int* in_sizes, int n_in,
                              void* d_out, int out_size)
{
    const float* h_in    = (const float*)d_in[0];
    const float* W_qkvz  = (const float*)d_in[1];
    const float* W_ba    = (const float*)d_in[2];
    const float* conv_w  = (const float*)d_in[3];
    const float* dt_bias = (const float*)d_in[4];
    const float* A_log   = (const float*)d_in[5];
    const float* norm_w  = (const float*)d_in[6];
    const float* W_out   = (const float*)d_in[7];
    float* out = (float*)d_out;

    float *qkvz, *qkv, *ba, *qhat, *khat, *qkdot, *oscan;
    float2* egbeta;
    __nv_bfloat16 *Wq_hi, *Wq_lo, *Wo_hi, *Wo_lo, *A_hi, *A_lo;
    cudaGetSymbolAddress((void**)&qkvz,   g_qkvz);
    cudaGetSymbolAddress((void**)&qkv,    g_qkv);
    cudaGetSymbolAddress((void**)&ba,     g_ba);
    cudaGetSymbolAddress((void**)&egbeta, g_egbeta);
    cudaGetSymbolAddress((void**)&qhat,   g_qhat);
    cudaGetSymbolAddress((void**)&khat,   g_khat);
    cudaGetSymbolAddress((void**)&qkdot,  g_qkdot);
    cudaGetSymbolAddress((void**)&oscan,  g_oscan);
    cudaGetSymbolAddress((void**)&Wq_hi,  g_Wq_hi);
    cudaGetSymbolAddress((void**)&Wq_lo,  g_Wq_lo);
    cudaGetSymbolAddress((void**)&Wo_hi,  g_Wo_hi);
    cudaGetSymbolAddress((void**)&Wo_lo,  g_Wo_lo);
    cudaGetSymbolAddress((void**)&A_hi,   g_A_hi);
    cudaGetSymbolAddress((void**)&A_lo,   g_A_lo);

    cudaFuncSetAttribute(gemm_tc, cudaFuncAttributeMaxDynamicSharedMemorySize, GT_SMEM);

    // prep
    {
        dim3 blk(32, 8);
        tr_split<<<dim3(QKVZ_N / 32, HID / 32), blk>>>(W_qkvz, Wq_hi, Wq_lo, HID, QKVZ_N);
        tr_split<<<dim3(HID / 32, VAL_DIM / 32), blk>>>(W_out, Wo_hi, Wo_lo, VAL_DIM, HID);
    }
    cvt_split<<<(T_SEQ * HID / 4 + 255) / 256, 256>>>(h_in, A_hi, A_lo, T_SEQ * HID / 4);

    // GEMM1: qkvz = h @ W_qkvz   [2048 x 12288], K=2048
    gemm_tc<<<dim3(T_SEQ / 128, QKVZ_N / 256), 256, GT_SMEM>>>(A_hi, A_lo, Wq_hi, Wq_lo, qkvz, QKVZ_N, HID);

    gemm_ba<<<T_SEQ / 64, 256>>>(h_in, W_ba, ba);
    conv_silu<<<((T_SEQ / 4) * CONV_DIM) / 256, 256>>>(qkvz, conv_w, qkv);
    gate_prep<<<(T_SEQ * NUM_V) / 256, 256>>>(ba, A_log, dt_bias, egbeta);
    l2norm_qk<<<(T_SEQ * 32) / 8, 256>>>(qkv, qhat, khat);
    qk_dot<<<(T_SEQ * NUM_K) / 8, 256>>>(qhat, khat, qkdot);
    gdn_scan<<<NUM_V * 16, 256>>>(qhat, khat, qkv, egbeta, qkdot, oscan);
    rms_gate_split<<<(T_SEQ * NUM_V) / 8, 256>>>(oscan, qkvz, norm_w, A_hi, A_lo);

    // GEMM2: out = gated @ W_out  [2048 x 2048], K=4096
    gemm_tc<<<dim3(T_SEQ / 128, HID / 256), 256, GT_SMEM>>>(A_hi, A_lo, Wo_hi, Wo_lo, out, HID, VAL_DIM);
}

// round 8
// speedup vs baseline: 1.9673x; 1.2037x over previous
#include <cuda_runtime.h>
#include <cuda_fp16.h>
#include <math.h>
#include <stdint.h>

// ---------------- problem constants ----------------
#define T_SEQ   2048
#define HID     2048
#define NUM_K   16
#define NUM_V   32
#define DK      128
#define DV      128
#define KEY_DIM 2048
#define VAL_DIM 4096
#define CONV_DIM 8192
#define QKVZ_N  12288
#define QSCALE  0.08838834764831845f

// ---------------- scratch ----------------
__device__ float  g_qkvz  [T_SEQ * QKVZ_N];
__device__ float  g_qkv   [T_SEQ * CONV_DIM];
__device__ float  g_ba    [T_SEQ * 64];
__device__ float2 g_egbeta[T_SEQ * NUM_V];
__device__ float  g_qhat  [T_SEQ * KEY_DIM];
__device__ float  g_khat  [T_SEQ * KEY_DIM];
__device__ float  g_qkdot [T_SEQ * NUM_K];
__device__ float  g_oscan [T_SEQ * VAL_DIM];

// fp16 operands: weights single fp16 (W^T), activations split hi/lo
__device__ __half g_Wq[QKVZ_N * HID];       // W_qkvz^T [N=12288][K=2048]
__device__ __half g_Wo[HID * VAL_DIM];      // W_out^T  [N=2048][K=4096]
__device__ __half g_A_hi[T_SEQ * VAL_DIM];
__device__ __half g_A_lo[T_SEQ * VAL_DIM];

// ---------------- helpers ----------------
__device__ __forceinline__ float sigmoidf_(float x) { return 1.0f / (1.0f + __expf(-x)); }
__device__ __forceinline__ float siluf_(float x)    { return x * sigmoidf_(x); }

__device__ __forceinline__ uint32_t smem_to_u32(const void* p) {
    uint32_t a;
    asm("{ .reg .u64 t; cvta.to.shared.u64 t, %1; cvt.u32.u64 %0, t; }" : "=r"(a) : "l"(p));
    return a;
}
__device__ __forceinline__ void ldsm4(uint32_t& r0, uint32_t& r1, uint32_t& r2, uint32_t& r3,
                                      uint32_t addr) {
    asm volatile("ldmatrix.sync.aligned.m8n8.x4.shared.b16 {%0,%1,%2,%3}, [%4];"
                 : "=r"(r0), "=r"(r1), "=r"(r2), "=r"(r3) : "r"(addr));
}
__device__ __forceinline__ void mma16816(float* d, const uint32_t* a, const uint32_t* b) {
    asm volatile("mma.sync.aligned.m16n8k16.row.col.f32.f16.f16.f32 "
                 "{%0,%1,%2,%3}, {%4,%5,%6,%7}, {%8,%9}, {%0,%1,%2,%3};"
                 : "+f"(d[0]), "+f"(d[1]), "+f"(d[2]), "+f"(d[3])
                 : "r"(a[0]), "r"(a[1]), "r"(a[2]), "r"(a[3]), "r"(b[0]), "r"(b[1]));
}

// ---------------- prep: fp32 -> fp16 hi/lo split ----------------
__global__ __launch_bounds__(256) void cvt_split(
    const float* __restrict__ x, __half* __restrict__ hi,
    __half* __restrict__ lo, int n4)
{
    int i = blockIdx.x * 256 + threadIdx.x;
    if (i >= n4) return;
    float4 v = ((const float4*)x)[i];
    __half h0 = __float2half_rn(v.x), h1 = __float2half_rn(v.y);
    __half h2 = __float2half_rn(v.z), h3 = __float2half_rn(v.w);
    __half l0 = __float2half_rn(v.x - __half2float(h0));
    __half l1 = __float2half_rn(v.y - __half2float(h1));
    __half l2 = __float2half_rn(v.z - __half2float(h2));
    __half l3 = __float2half_rn(v.w - __half2float(h3));
    union { __half2 h2v[2]; uint2 u; } H, L;
    H.h2v[0] = __halves2half2(h0, h1); H.h2v[1] = __halves2half2(h2, h3);
    L.h2v[0] = __halves2half2(l0, l1); L.h2v[1] = __halves2half2(l2, l3);
    ((uint2*)hi)[i] = H.u;
    ((uint2*)lo)[i] = L.u;
}

// ---------------- prep: W [K][N] fp32 -> W^T [N][K] fp16 ----------------
__global__ __launch_bounds__(256) void tr_half(
    const float* __restrict__ W, __half* __restrict__ out, int K, int N)
{
    __shared__ float t[32][33];
    int n0 = blockIdx.x * 32, k0 = blockIdx.y * 32;
    int tx = threadIdx.x, ty = threadIdx.y;
#pragma unroll
    for (int j = 0; j < 4; ++j)
        t[ty + j * 8][tx] = W[(size_t)(k0 + ty + j * 8) * N + n0 + tx];
    __syncthreads();
#pragma unroll
    for (int j = 0; j < 4; ++j) {
        int n = ty + j * 8;
        out[(size_t)(n0 + n) * K + k0 + tx] = __float2half_rn(t[tx][n]);
    }
}

// ---------------- mma.sync GEMM: 128x256 CTA, 64x64 warp tiles, cp.async 3-stage ----------------
// A split fp16 hi/lo (2 passes), B single fp16. C = (Ah+Al) @ B^T.
#define SSTR   80
#define SZ_A   (128 * SSTR)
#define SZ_B   (256 * SSTR)
#define BUF_SZ (2 * SZ_A + SZ_B)        // 40960
#define GT_SMEM (3 * BUF_SZ)            // 122880

template<int ITERS>
__device__ __forceinline__ void cpa_stage(uint32_t sdst, const char* g, int Kb, int tid) {
#pragma unroll
    for (int i = 0; i < ITERS; ++i) {
        int idx = tid + i * 256;
        int row = idx >> 2;
        int q   = (idx & 3) << 4;
        uint32_t d = sdst + row * SSTR + q;
        const char* s = g + (size_t)row * Kb + q;
        asm volatile("cp.async.cg.shared.global [%0], [%1], 16;" :: "r"(d), "l"(s));
    }
}

__global__ __launch_bounds__(256, 1) void gemm_tc(
    const __half* __restrict__ Ahi, const __half* __restrict__ Alo,
    const __half* __restrict__ B, float* __restrict__ C, int N, int K)
{
    extern __shared__ __align__(128) char smem[];
    const uint32_t sb = smem_to_u32(smem);

    const int tid  = threadIdx.x;
    const int wid  = tid >> 5;
    const int lane = tid & 31;
    const int bm   = blockIdx.x * 128;
    const int bn   = blockIdx.y * 256;
    const int wm   = (wid >> 2) * 64;
    const int wn   = (wid & 3) * 64;
    const int Kb   = K * 2;

    const char* gAh = (const char*)(Ahi + (size_t)bm * K);
    const char* gAl = (const char*)(Alo + (size_t)bm * K);
    const char* gB  = (const char*)(B   + (size_t)bn * K);

    float acc[4][8][4];
#pragma unroll
    for (int i = 0; i < 4; ++i)
#pragma unroll
        for (int j = 0; j < 8; ++j)
#pragma unroll
            for (int r = 0; r < 4; ++r) acc[i][j][r] = 0.0f;

    const uint32_t aoff = (lane & 15) * SSTR + ((lane >> 4) << 4);
    const uint32_t boff = ((lane & 7) + ((lane >> 4) << 3)) * SSTR + (((lane >> 3) & 1) << 4);

    const int nk = K >> 5;

#pragma unroll
    for (int p = 0; p < 2; ++p) {
        uint32_t sbuf = sb + p * BUF_SZ;
        size_t ko = (size_t)p * 64;
        cpa_stage<2>(sbuf,            gAh + ko, Kb, tid);
        cpa_stage<2>(sbuf + SZ_A,     gAl + ko, Kb, tid);
        cpa_stage<4>(sbuf + 2 * SZ_A, gB  + ko, Kb, tid);
        asm volatile("cp.async.commit_group;");
    }

    int buf = 0;
    for (int kt = 0; kt < nk; ++kt) {
        asm volatile("cp.async.wait_group 1;");
        __syncthreads();

        if (kt + 2 < nk) {
            int nb = (buf + 2) % 3;
            uint32_t sbuf = sb + nb * BUF_SZ;
            size_t ko = (size_t)(kt + 2) * 64;
            cpa_stage<2>(sbuf,            gAh + ko, Kb, tid);
            cpa_stage<2>(sbuf + SZ_A,     gAl + ko, Kb, tid);
            cpa_stage<4>(sbuf + 2 * SZ_A, gB  + ko, Kb, tid);
        }
        asm volatile("cp.async.commit_group;");

        const uint32_t sAh = sb + buf * BUF_SZ;
        const uint32_t sAl = sAh + SZ_A;
        const uint32_t sB  = sAh + 2 * SZ_A;

#pragma unroll
        for (int ks = 0; ks < 2; ++ks) {
            const uint32_t kb = ks * 32;
            uint32_t ah[4][4], al[4][4];
#pragma unroll
            for (int mt = 0; mt < 4; ++mt) {
                uint32_t base = (wm + mt * 16) * SSTR + aoff + kb;
                ldsm4(ah[mt][0], ah[mt][1], ah[mt][2], ah[mt][3], sAh + base);
                ldsm4(al[mt][0], al[mt][1], al[mt][2], al[mt][3], sAl + base);
            }
#pragma unroll
            for (int pr = 0; pr < 4; ++pr) {
                uint32_t bbase = (wn + pr * 16) * SSTR + boff + kb;
                uint32_t h0, h1, h2, h3;
                ldsm4(h0, h1, h2, h3, sB + bbase);
                uint32_t b0[2] = {h0, h1}, b1[2] = {h2, h3};
#pragma unroll
                for (int mt = 0; mt < 4; ++mt) {
                    mma16816(acc[mt][2 * pr],     ah[mt], b0);
                    mma16816(acc[mt][2 * pr + 1], ah[mt], b1);
                    mma16816(acc[mt][2 * pr],     al[mt], b0);
                    mma16816(acc[mt][2 * pr + 1], al[mt], b1);
                }
            }
        }
        buf = (buf + 1) % 3;
    }

    const int g  = lane >> 2;
    const int tg = lane & 3;
#pragma unroll
    for (int mt = 0; mt < 4; ++mt) {
#pragma unroll
        for (int nt = 0; nt < 8; ++nt) {
            const float* d = acc[mt][nt];
            size_t r = (size_t)(bm + wm + mt * 16 + g) * N + bn + wn + nt * 8 + tg * 2;
            *(float2*)&C[r] = make_float2(d[0], d[1]);
            *(float2*)&C[r + 8 * (size_t)N] = make_float2(d[2], d[3]);
        }
    }
}

// ---------------- tiled small GEMM: ba = h @ W_ba (2048x64, K=2048) ----------------
__global__ __launch_bounds__(256) void gemm_ba(
    const float* __restrict__ A, const float* __restrict__ B, float* __restrict__ C)
{
    __shared__ float sh[64][65];
    __shared__ float sB[64][65];
    const int tid = threadIdx.x;
    const int col = tid & 63;
    const int rg  = tid >> 6;
    const int br  = blockIdx.x * 64;

    float acc[16];
#pragma unroll
    for (int r = 0; r < 16; ++r) acc[r] = 0.0f;

    for (int kt = 0; kt < HID / 64; ++kt) {
#pragma unroll
        for (int i = 0; i < 16; ++i) {
            int idx = tid + i * 256;
            int row = idx >> 6, kk = idx & 63;
            sh[row][kk] = A[(size_t)(br + row) * HID + kt * 64 + kk];
            sB[row][kk] = B[(size_t)(kt * 64 + row) * 64 + kk];
        }
        __syncthreads();
#pragma unroll 16
        for (int kk = 0; kk < 64; ++kk) {
            float b = sB[kk][col];
#pragma unroll
            for (int r = 0; r < 16; ++r)
                acc[r] = fmaf(sh[rg * 16 + r][kk], b, acc[r]);
        }
        __syncthreads();
    }
#pragma unroll
    for (int r = 0; r < 16; ++r)
        C[(size_t)(br + rg * 16 + r) * 64 + col] = acc[r];
}

// ---------------- causal depthwise conv (K=4) + SiLU, 4 t per thread ----------------
__global__ __launch_bounds__(256) void conv_silu(
    const float* __restrict__ qkvz, const float* __restrict__ conv_w,
    float* __restrict__ out)
{
    int idx = blockIdx.x * blockDim.x + threadIdx.x;
    if (idx >= (T_SEQ / 4) * CONV_DIM) return;
    int tq = idx >> 13;
    int c  = idx & (CONV_DIM - 1);
    int t0 = tq * 4;
    const float* w = conv_w + c * 4;
    float xv[7];
#pragma unroll
    for (int j = 0; j < 7; ++j) {
        int tt = t0 - 3 + j;
        xv[j] = (tt >= 0) ? qkvz[(size_t)tt * QKVZ_N + c] : 0.0f;
    }
#pragma unroll
    for (int i = 0; i < 4; ++i) {
        float a = w[0] * xv[i];
        a = fmaf(w[1], xv[i + 1], a);
        a = fmaf(w[2], xv[i + 2], a);
        a = fmaf(w[3], xv[i + 3], a);
        out[(size_t)(t0 + i) * CONV_DIM + c] = siluf_(a);
    }
}

// ---------------- gating ----------------
__global__ __launch_bounds__(256) void gate_prep(
    const float* __restrict__ ba, const float* __restrict__ A_log,
    const float* __restrict__ dt_bias, float2* __restrict__ egbeta)
{
    int i = blockIdx.x * blockDim.x + threadIdx.x;
    if (i >= T_SEQ * NUM_V) return;
    int t = i >> 5;
    int h = i & 31;
    float b = ba[(size_t)t * 64 + h];
    float a = ba[(size_t)t * 64 + 32 + h];
    float x = a + dt_bias[h];
    float sp = (x > 20.0f) ? x : log1pf(expf(x));
    float g = -expf(A_log[h]) * sp;
    egbeta[i] = make_float2(expf(g), sigmoidf_(b));
}

// ---------------- l2norm of q and k; scale folded into q ----------------
__global__ __launch_bounds__(256) void l2norm_qk(
    const float* __restrict__ qkv, float* __restrict__ qhat, float* __restrict__ khat)
{
    int gid  = blockIdx.x * 8 + (threadIdx.x >> 5);
    int lane = threadIdx.x & 31;
    int t   = gid >> 5;
    int sub = gid & 31;
    int kh  = sub & 15;
    int isK = sub >> 4;
    const float* src = qkv + (size_t)t * CONV_DIM + isK * KEY_DIM + kh * DK;
    float4 x = *(const float4*)(src + lane * 4);
    float s = x.x * x.x + x.y * x.y + x.z * x.z + x.w * x.w;
#pragma unroll
    for (int off = 16; off > 0; off >>= 1) s += __shfl_xor_sync(0xffffffffu, s, off);
    float r = rsqrtf(s + 1e-6f);
    if (!isK) r *= QSCALE;
    float* dst = (isK ? khat : qhat) + (size_t)t * KEY_DIM + kh * DK;
    *(float4*)(dst + lane * 4) = make_float4(x.x * r, x.y * r, x.z * r, x.w * r);
}

// ---------------- qk dot ----------------
__global__ __launch_bounds__(256) void qk_dot(
    const float* __restrict__ qhat, const float* __restrict__ khat,
    float* __restrict__ qk)
{
    int gid  = blockIdx.x * 8 + (threadIdx.x >> 5);
    int lane = threadIdx.x & 31;
    int t  = gid >> 4;
    int kh = gid & 15;
    const float4* qp = (const float4*)(qhat + (size_t)t * KEY_DIM + kh * DK) + lane;
    const float4* kp = (const float4*)(khat + (size_t)t * KEY_DIM + kh * DK) + lane;
    float4 q = *qp, k = *kp;
    float s = q.x * k.x + q.y * k.y + q.z * k.z + q.w * k.w;
#pragma unroll
    for (int off = 16; off > 0; off >>= 1) s += __shfl_xor_sync(0xffffffffu, s, off);
    if (lane == 0) qk[t * NUM_K + kh] = s;
}

// ---------------- gated delta scan: one warp per (head, v-column) ----------------
__global__ __launch_bounds__(256) void gdn_scan(
    const float* __restrict__ qhat, const float* __restrict__ khat,
    const float* __restrict__ qkv, const float2* __restrict__ egbeta,
    const float* __restrict__ qk, float* __restrict__ o)
{
    const int warp = threadIdx.x >> 5;
    const int lane = threadIdx.x & 31;
    const int h   = blockIdx.x >> 4;
    const int col = ((blockIdx.x & 15) << 3) + warp;
    const int kh  = h >> 1;

    const float4* kp = (const float4*)(khat + kh * DK) + lane;
    const float4* qp = (const float4*)(qhat + kh * DK) + lane;
    const float*  vp = qkv + 2 * KEY_DIM + h * DV + col;
    const float2* ep = egbeta + h;
    const float*  xp = qk + kh;
    float*        op = o + h * DV + col;

    float S0 = 0.f, S1 = 0.f, S2 = 0.f, S3 = 0.f;

    float4 kk = *kp, qq = *qp;
    float  vt = *vp;
    float2 eb = *ep;
    float  xq = *xp;

    for (int t = 0; t < T_SEQ; ++t) {
        float4 kk_n, qq_n; float vt_n, xq_n; float2 eb_n;
        if (t < T_SEQ - 1) {
            kp += KEY_DIM / 4; qp += KEY_DIM / 4; vp += CONV_DIM; ep += NUM_V; xp += NUM_K;
            kk_n = *kp; qq_n = *qp; vt_n = *vp; eb_n = *ep; xq_n = *xp;
        } else {
            kk_n = kk; qq_n = qq; vt_n = vt; eb_n = eb; xq_n = xq;
        }

        float dk = kk.x * S0 + kk.y * S1 + kk.z * S2 + kk.w * S3;
        float dq = qq.x * S0 + qq.y * S1 + qq.z * S2 + qq.w * S3;
#pragma unroll
        for (int off = 16; off > 0; off >>= 1) {
            dk += __shfl_xor_sync(0xffffffffu, dk, off);
            dq += __shfl_xor_sync(0xffffffffu, dq, off);
        }
        const float eg = eb.x, beta = eb.y;
        const float delta = (vt - eg * dk) * beta;
        const float ot    = fmaf(eg, dq, xq * delta);
        S0 = fmaf(S0, eg, kk.x * delta);
        S1 = fmaf(S1, eg, kk.y * delta);
        S2 = fmaf(S2, eg, kk.z * delta);
        S3 = fmaf(S3, eg, kk.w * delta);
        if (lane == 0) *op = ot;
        op += VAL_DIM;
        kk = kk_n; qq = qq_n; vt = vt_n; eb = eb_n; xq = xq_n;
    }
}

// ---------------- RMSNorm * norm_w * silu(z), write fp16 hi/lo directly ----------------
__global__ __launch_bounds__(256) void rms_gate_split(
    const float* __restrict__ o, const float* __restrict__ qkvz,
    const float* __restrict__ norm_w,
    __half* __restrict__ hi, __half* __restrict__ lo)
{
    int gid  = blockIdx.x * 8 + (threadIdx.x >> 5);
    int lane = threadIdx.x & 31;
    int t = gid >> 5;
    int h = gid & 31;
    const float* orow = o + (size_t)t * VAL_DIM + h * DV;
    float4 x = *(const float4*)(orow + lane * 4);
    float s = x.x * x.x + x.y * x.y + x.z * x.z + x.w * x.w;
#pragma unroll
    for (int off = 16; off > 0; off >>= 1) s += __shfl_xor_sync(0xffffffffu, s, off);
    float r = rsqrtf(s * (1.0f / DV) + 1e-6f);
    float4 z  = *(const float4*)(qkvz + (size_t)t * QKVZ_N + 2 * KEY_DIM + VAL_DIM + h * DV + lane * 4);
    float4 nw = *(const float4*)(norm_w + lane * 4);
    float4 y;
    y.x = x.x * r * nw.x * siluf_(z.x);
    y.y = x.y * r * nw.y * siluf_(z.y);
    y.z = x.z * r * nw.z * siluf_(z.z);
    y.w = x.w * r * nw.w * siluf_(z.w);
    __half h0 = __float2half_rn(y.x), h1 = __float2half_rn(y.y);
    __half h2 = __float2half_rn(y.z), h3 = __float2half_rn(y.w);
    __half l0 = __float2half_rn(y.x - __half2float(h0));
    __half l1 = __float2half_rn(y.y - __half2float(h1));
    __half l2 = __float2half_rn(y.z - __half2float(h2));
    __half l3 = __float2half_rn(y.w - __half2float(h3));
    union { __half2 h2v[2]; uint2 u; } H, L;
    H.h2v[0] = __halves2half2(h0, h1); H.h2v[1] = __halves2half2(h2, h3);
    L.h2v[0] = __halves2half2(l0, l1); L.h2v[1] = __halves2half2(l2, l3);
    int i4 = (t * VAL_DIM + h * DV) / 4 + lane;
    ((uint2*)hi)[i4] = H.u;
    ((uint2*)lo)[i4] = L.u;
}

// ---------------- launch ----------------
extern "C" void kernel_launch(void* const* d_in, const int* in_sizes, int n_in,
                              void* d_out, int out_size)
{
    const float* h_in    = (const float*)d_in[0];
    const float* W_qkvz  = (const float*)d_in[1];
    const float* W_ba    = (const float*)d_in[2];
    const float* conv_w  = (const float*)d_in[3];
    const float* dt_bias = (const float*)d_in[4];
    const float* A_log   = (const float*)d_in[5];
    const float* norm_w  = (const float*)d_in[6];
    const float* W_out   = (const float*)d_in[7];
    float* out = (float*)d_out;

    float *qkvz, *qkv, *ba, *qhat, *khat, *qkdot, *oscan;
    float2* egbeta;
    __half *Wq, *Wo, *A_hi, *A_lo;
    cudaGetSymbolAddress((void**)&qkvz,   g_qkvz);
    cudaGetSymbolAddress((void**)&qkv,    g_qkv);
    cudaGetSymbolAddress((void**)&ba,     g_ba);
    cudaGetSymbolAddress((void**)&egbeta, g_egbeta);
    cudaGetSymbolAddress((void**)&qhat,   g_qhat);
    cudaGetSymbolAddress((void**)&khat,   g_khat);
    cudaGetSymbolAddress((void**)&qkdot,  g_qkdot);
    cudaGetSymbolAddress((void**)&oscan,  g_oscan);
    cudaGetSymbolAddress((void**)&Wq,     g_Wq);
    cudaGetSymbolAddress((void**)&Wo,     g_Wo);
    cudaGetSymbolAddress((void**)&A_hi,   g_A_hi);
    cudaGetSymbolAddress((void**)&A_lo,   g_A_lo);

    cudaFuncSetAttribute(gemm_tc, cudaFuncAttributeMaxDynamicSharedMemorySize, GT_SMEM);

    // prep
    {
        dim3 blk(32, 8);
        tr_half<<<dim3(QKVZ_N / 32, HID / 32), blk>>>(W_qkvz, Wq, HID, QKVZ_N);
        tr_half<<<dim3(HID / 32, VAL_DIM / 32), blk>>>(W_out, Wo, VAL_DIM, HID);
    }
    cvt_split<<<(T_SEQ * HID / 4 + 255) / 256, 256>>>(h_in, A_hi, A_lo, T_SEQ * HID / 4);

    // GEMM1: qkvz = h @ W_qkvz   [2048 x 12288], K=2048
    gemm_tc<<<dim3(T_SEQ / 128, QKVZ_N / 256), 256, GT_SMEM>>>(A_hi, A_lo, Wq, qkvz, QKVZ_N, HID);

    gemm_ba<<<T_SEQ / 64, 256>>>(h_in, W_ba, ba);
    conv_silu<<<((T_SEQ / 4) * CONV_DIM) / 256, 256>>>(qkvz, conv_w, qkv);
    gate_prep<<<(T_SEQ * NUM_V) / 256, 256>>>(ba, A_log, dt_bias, egbeta);
    l2norm_qk<<<(T_SEQ * 32) / 8, 256>>>(qkv, qhat, khat);
    qk_dot<<<(T_SEQ * NUM_K) / 8, 256>>>(qhat, khat, qkdot);
    gdn_scan<<<NUM_V * 16, 256>>>(qhat, khat, qkv, egbeta, qkdot, oscan);
    rms_gate_split<<<(T_SEQ * NUM_V) / 8, 256>>>(oscan, qkvz, norm_w, A_hi, A_lo);

    // GEMM2: out = gated @ W_out  [2048 x 2048], K=4096
    gemm_tc<<<dim3(T_SEQ / 128, HID / 256), 256, GT_SMEM>>>(A_hi, A_lo, Wo, out, HID, VAL_DIM);
}